// round 1
// baseline (speedup 1.0000x reference)
#include <cuda_runtime.h>
#include <cuda_bf16.h>
#include <cstdint>

#define NTREES 32
#define NINT   15
#define NLEAF  16
#define BATCH  8192
#define DFEAT  1024
#define NCLS   100
#define NTP    512   // padded tree-leaf columns (32 trees * 16 slots, slot 15 pad)
#define NCP    128   // padded class rows for GEMM2 B matrix

// ---------------- static device scratch (allocation-free contract) ----------------
__device__ __align__(16) __nv_bfloat16 g_xh[BATCH * DFEAT];
__device__ __align__(16) __nv_bfloat16 g_xl[BATCH * DFEAT];
__device__ __align__(16) __nv_bfloat16 g_swh[NTP * DFEAT];
__device__ __align__(16) __nv_bfloat16 g_swl[NTP * DFEAT];
__device__ __align__(16) float         g_sbp[NTP];
__device__ __align__(16) __nv_bfloat16 g_lph[BATCH * NTP];
__device__ __align__(16) __nv_bfloat16 g_lpl[BATCH * NTP];
__device__ __align__(16) __nv_bfloat16 g_Mth[NCP * NTP];
__device__ __align__(16) __nv_bfloat16 g_Mtl[NCP * NTP];
__device__ float g_w[NTREES];
__device__ float g_invtemp;

// ---------------- PTX helpers ----------------
__device__ __forceinline__ void cp16(uint32_t s, const void* g) {
    asm volatile("cp.async.cg.shared.global [%0], [%1], 16;\n" :: "r"(s), "l"(g));
}
__device__ __forceinline__ void cp_commit() { asm volatile("cp.async.commit_group;\n" ::); }
__device__ __forceinline__ void cp_wait0()  { asm volatile("cp.async.wait_group 0;\n" ::); }
__device__ __forceinline__ void cp_wait1()  { asm volatile("cp.async.wait_group 1;\n" ::); }

__device__ __forceinline__ void ldsm4(uint32_t& r0, uint32_t& r1, uint32_t& r2, uint32_t& r3, uint32_t a) {
    asm volatile("ldmatrix.sync.aligned.m8n8.x4.shared.b16 {%0,%1,%2,%3}, [%4];\n"
                 : "=r"(r0), "=r"(r1), "=r"(r2), "=r"(r3) : "r"(a));
}
__device__ __forceinline__ void mma_bf16(float* c, const uint32_t* a, uint32_t b0, uint32_t b1) {
    asm volatile("mma.sync.aligned.m16n8k16.row.col.f32.bf16.bf16.f32 "
                 "{%0,%1,%2,%3}, {%4,%5,%6,%7}, {%8,%9}, {%0,%1,%2,%3};\n"
                 : "+f"(c[0]), "+f"(c[1]), "+f"(c[2]), "+f"(c[3])
                 : "r"(a[0]), "r"(a[1]), "r"(a[2]), "r"(a[3]), "r"(b0), "r"(b1));
}

__device__ __forceinline__ uint32_t pack_bf16x2(__nv_bfloat16 lo, __nv_bfloat16 hi) {
    return ((uint32_t)__bfloat16_as_ushort(hi) << 16) | (uint32_t)__bfloat16_as_ushort(lo);
}

// ---------------- prep kernels ----------------
__global__ void prep_scalars_kernel(const float* __restrict__ tw, const float* __restrict__ log_temp) {
    int lane = threadIdx.x;
    float t = expf(log_temp[0]);
    t = fminf(fmaxf(t, 0.1f), 5.0f);
    if (lane == 0) g_invtemp = 1.0f / t;
    float v = tw[lane];
    float m = v;
    #pragma unroll
    for (int o = 16; o; o >>= 1) m = fmaxf(m, __shfl_xor_sync(0xffffffffu, m, o));
    float e = expf(v - m);
    float s = e;
    #pragma unroll
    for (int o = 16; o; o >>= 1) s += __shfl_xor_sync(0xffffffffu, s, o);
    g_w[lane] = e / s;
}

__global__ void prep_sb_kernel(const float* __restrict__ sb) {
    int r = blockIdx.x * blockDim.x + threadIdx.x;
    if (r < NTP) {
        int t = r >> 4, i = r & 15;
        g_sbp[r] = (i < NINT) ? sb[t * NINT + i] : 0.0f;
    }
}

// one block per (tree, leaf) column; builds M^T [class, tree*16+leaf] with tw weight folded, hi/lo split
__global__ void prep_leaf_kernel(const float* __restrict__ ll) {
    __shared__ float red[4], red2[4];
    int col = blockIdx.x;            // t*16 + l
    int t = col >> 4;
    int c = threadIdx.x;             // 0..127
    float invt = g_invtemp;
    float v = (c < NCLS) ? ll[col * NCLS + c] : -1e30f;
    float m = v;
    #pragma unroll
    for (int o = 16; o; o >>= 1) m = fmaxf(m, __shfl_xor_sync(0xffffffffu, m, o));
    if ((threadIdx.x & 31) == 0) red[threadIdx.x >> 5] = m;
    __syncthreads();
    m = fmaxf(fmaxf(red[0], red[1]), fmaxf(red[2], red[3]));
    float e = (c < NCLS) ? expf((v - m) * invt) : 0.0f;
    float s = e;
    #pragma unroll
    for (int o = 16; o; o >>= 1) s += __shfl_xor_sync(0xffffffffu, s, o);
    if ((threadIdx.x & 31) == 0) red2[threadIdx.x >> 5] = s;
    __syncthreads();
    s = red2[0] + red2[1] + red2[2] + red2[3];
    float p = (c < NCLS) ? (g_w[t] * e / s) : 0.0f;
    __nv_bfloat16 h = __float2bfloat16_rn(p);
    g_Mth[c * NTP + col] = h;
    g_Mtl[c * NTP + col] = __float2bfloat16_rn(p - __bfloat162float(h));
}

__global__ void split_x_kernel(const float* __restrict__ x) {
    int i = (blockIdx.x * blockDim.x + threadIdx.x) * 4;
    float4 v = *reinterpret_cast<const float4*>(x + i);
    __nv_bfloat16 h0 = __float2bfloat16_rn(v.x), h1 = __float2bfloat16_rn(v.y);
    __nv_bfloat16 h2 = __float2bfloat16_rn(v.z), h3 = __float2bfloat16_rn(v.w);
    __nv_bfloat16 l0 = __float2bfloat16_rn(v.x - __bfloat162float(h0));
    __nv_bfloat16 l1 = __float2bfloat16_rn(v.y - __bfloat162float(h1));
    __nv_bfloat16 l2 = __float2bfloat16_rn(v.z - __bfloat162float(h2));
    __nv_bfloat16 l3 = __float2bfloat16_rn(v.w - __bfloat162float(h3));
    uint2 H, L;
    H.x = pack_bf16x2(h0, h1); H.y = pack_bf16x2(h2, h3);
    L.x = pack_bf16x2(l0, l1); L.y = pack_bf16x2(l2, l3);
    *reinterpret_cast<uint2*>(&g_xh[i]) = H;
    *reinterpret_cast<uint2*>(&g_xl[i]) = L;
}

__global__ void split_sw_kernel(const float* __restrict__ sw) {
    int idx = (blockIdx.x * blockDim.x + threadIdx.x) * 4;   // over NTP*DFEAT
    int row = idx >> 10;
    int k = idx & 1023;
    int t = row >> 4, i = row & 15;
    float4 v = make_float4(0.f, 0.f, 0.f, 0.f);
    if (i < NINT) v = *reinterpret_cast<const float4*>(&sw[(size_t)(t * NINT + i) * DFEAT + k]);
    __nv_bfloat16 h0 = __float2bfloat16_rn(v.x), h1 = __float2bfloat16_rn(v.y);
    __nv_bfloat16 h2 = __float2bfloat16_rn(v.z), h3 = __float2bfloat16_rn(v.w);
    __nv_bfloat16 l0 = __float2bfloat16_rn(v.x - __bfloat162float(h0));
    __nv_bfloat16 l1 = __float2bfloat16_rn(v.y - __bfloat162float(h1));
    __nv_bfloat16 l2 = __float2bfloat16_rn(v.z - __bfloat162float(h2));
    __nv_bfloat16 l3 = __float2bfloat16_rn(v.w - __bfloat162float(h3));
    uint2 H, L;
    H.x = pack_bf16x2(h0, h1); H.y = pack_bf16x2(h2, h3);
    L.x = pack_bf16x2(l0, l1); L.y = pack_bf16x2(l2, l3);
    *reinterpret_cast<uint2*>(&g_swh[idx]) = H;
    *reinterpret_cast<uint2*>(&g_swl[idx]) = L;
}

// ---------------- GEMM1: sp = sigmoid((x@sw^T + sb)/temp), fused leaf-prob epilogue ----------------
// Block tile 128(M) x 64(N=4 trees) x 16(K), 2-stage cp.async pipeline, 3-pass bf16 split.
#define G1_STAGE 18432   // Ah 6144 + Al 6144 + Bh 3072 + Bl 3072 (rows padded to 24 bf16 = 48 B)

__global__ void __launch_bounds__(256, 1) gemm1_kernel() {
    __shared__ __align__(16) unsigned char smem[2 * G1_STAGE];
    const uint32_t sbase = (uint32_t)__cvta_generic_to_shared(smem);
    const int tid = threadIdx.x;
    const int m0 = blockIdx.x * 128;
    const int n0 = blockIdx.y * 64;
    const int wid = tid >> 5, lane = tid & 31;
    const int wm = wid >> 2, wn = wid & 3;

    float acc[4][2][4];
    #pragma unroll
    for (int i = 0; i < 4; i++)
        #pragma unroll
        for (int j = 0; j < 2; j++)
            #pragma unroll
            for (int k = 0; k < 4; k++) acc[i][j][k] = 0.0f;

    const int arow = tid >> 1, ach = tid & 1;        // 128 rows x 2 16B chunks
    const int bt = tid & 127;
    const int brow = bt >> 1, bch = bt & 1;          // 64 rows x 2 chunks

    auto issue = [&](int s, int k0) {
        uint32_t st = sbase + s * G1_STAGE;
        uint32_t sa = st + arow * 48 + ach * 16;
        cp16(sa,        &g_xh[(m0 + arow) * DFEAT + k0 + ach * 8]);
        cp16(sa + 6144, &g_xl[(m0 + arow) * DFEAT + k0 + ach * 8]);
        uint32_t sbm = st + 12288 + (tid >= 128 ? 3072 : 0) + brow * 48 + bch * 16;
        const __nv_bfloat16* bsrc = (tid >= 128)
            ? &g_swl[(n0 + brow) * DFEAT + k0 + bch * 8]
            : &g_swh[(n0 + brow) * DFEAT + k0 + bch * 8];
        cp16(sbm, bsrc);
    };

    issue(0, 0);
    cp_commit();

    const uint32_t aoff = (uint32_t)((wm * 64 + (lane & 15)) * 48 + (lane >> 4) * 16);
    const uint32_t boff = (uint32_t)((wn * 16 + (lane & 7) + ((lane >> 4) << 3)) * 48 + (((lane >> 3) & 1) << 4));

    #pragma unroll 1
    for (int kt = 0; kt < DFEAT / 16; ++kt) {
        if (kt + 1 < DFEAT / 16) { issue((kt + 1) & 1, (kt + 1) * 16); cp_commit(); cp_wait1(); }
        else cp_wait0();
        __syncthreads();
        uint32_t st = sbase + (kt & 1) * G1_STAGE;
        uint32_t ah[4][4], al[4][4], bh[4], bl[4];
        #pragma unroll
        for (int mf = 0; mf < 4; ++mf) {
            ldsm4(ah[mf][0], ah[mf][1], ah[mf][2], ah[mf][3], st + aoff + mf * 768);
            ldsm4(al[mf][0], al[mf][1], al[mf][2], al[mf][3], st + 6144 + aoff + mf * 768);
        }
        ldsm4(bh[0], bh[1], bh[2], bh[3], st + 12288 + boff);
        ldsm4(bl[0], bl[1], bl[2], bl[3], st + 15360 + boff);
        #pragma unroll
        for (int mf = 0; mf < 4; ++mf) {
            #pragma unroll
            for (int nf = 0; nf < 2; ++nf) {
                mma_bf16(acc[mf][nf], ah[mf], bh[nf * 2], bh[nf * 2 + 1]);
                mma_bf16(acc[mf][nf], ah[mf], bl[nf * 2], bl[nf * 2 + 1]);
                mma_bf16(acc[mf][nf], al[mf], bh[nf * 2], bh[nf * 2 + 1]);
            }
        }
        __syncthreads();
    }

    // Epilogue 1: sigmoid -> sp scratch in smem (stride 68 floats)
    float* sp = reinterpret_cast<float*>(smem);
    const float invt = g_invtemp;
    #pragma unroll
    for (int mf = 0; mf < 4; ++mf) {
        int r = wm * 64 + mf * 16 + (lane >> 2);
        #pragma unroll
        for (int nf = 0; nf < 2; ++nf) {
            int c = wn * 16 + nf * 8 + (lane & 3) * 2;
            float b0 = g_sbp[n0 + c], b1 = g_sbp[n0 + c + 1];
            #pragma unroll
            for (int h = 0; h < 2; ++h) {
                float z0 = (acc[mf][nf][h * 2 + 0] + b0) * invt;
                float z1 = (acc[mf][nf][h * 2 + 1] + b1) * invt;
                sp[(r + h * 8) * 68 + c]     = 1.0f / (1.0f + __expf(-z0));
                sp[(r + h * 8) * 68 + c + 1] = 1.0f / (1.0f + __expf(-z1));
            }
        }
    }
    __syncthreads();

    // Epilogue 2: each (row, tree) -> 16 leaf path-products, store bf16 hi/lo
    #pragma unroll
    for (int pass = 0; pass < 2; ++pass) {
        int task = pass * 256 + tid;      // 512 tasks = 128 rows * 4 trees
        int row = task >> 2, tr = task & 3;
        float s[15];
        #pragma unroll
        for (int i = 0; i < 15; ++i) s[i] = sp[row * 68 + tr * 16 + i];
        alignas(16) __nv_bfloat16 ph[16];
        alignas(16) __nv_bfloat16 pl[16];
        #pragma unroll
        for (int l = 0; l < 16; ++l) {
            float p = 1.0f;
            int ni = l + 15;
            #pragma unroll
            for (int d = 0; d < 4; ++d) {
                int pi = (ni - 1) >> 1;
                float f = s[pi];
                p *= (ni & 1) ? (1.0f - f) : f;   // even child -> sp, odd -> 1-sp
                ni = pi;
            }
            __nv_bfloat16 h = __float2bfloat16_rn(p);
            ph[l] = h;
            pl[l] = __float2bfloat16_rn(p - __bfloat162float(h));
        }
        size_t off = (size_t)(m0 + row) * NTP + n0 + tr * 16;
        const uint4* uh = reinterpret_cast<const uint4*>(ph);
        const uint4* ul = reinterpret_cast<const uint4*>(pl);
        reinterpret_cast<uint4*>(&g_lph[off])[0] = uh[0];
        reinterpret_cast<uint4*>(&g_lph[off])[1] = uh[1];
        reinterpret_cast<uint4*>(&g_lpl[off])[0] = ul[0];
        reinterpret_cast<uint4*>(&g_lpl[off])[1] = ul[1];
    }
}

// ---------------- GEMM2: out = lp[8192,512] @ M^T, 128x128x16 tiles, split bf16 ----------------
__global__ void __launch_bounds__(256, 1) gemm2_kernel(float* __restrict__ out) {
    __shared__ __align__(16) unsigned char smem[24576]; // Ah 6144 | Al 6144 | Bh 6144 | Bl 6144
    const uint32_t sbase = (uint32_t)__cvta_generic_to_shared(smem);
    const int tid = threadIdx.x;
    const int m0 = blockIdx.x * 128;
    const int wid = tid >> 5, lane = tid & 31;
    const int wm = wid >> 2, wn = wid & 3;

    float acc[4][4][4];
    #pragma unroll
    for (int i = 0; i < 4; i++)
        #pragma unroll
        for (int j = 0; j < 4; j++)
            #pragma unroll
            for (int k = 0; k < 4; k++) acc[i][j][k] = 0.0f;

    const int arow = tid >> 1, ach = tid & 1;    // 128 rows x 2 chunks for both A and B tiles
    const uint32_t aoff = (uint32_t)((wm * 64 + (lane & 15)) * 48 + (lane >> 4) * 16);
    const uint32_t boff = (uint32_t)((wn * 32 + (lane & 7) + ((lane >> 4) << 3)) * 48 + (((lane >> 3) & 1) << 4));

    #pragma unroll 1
    for (int kt = 0; kt < NTP / 16; ++kt) {
        int k0 = kt * 16;
        uint32_t sa = sbase + arow * 48 + ach * 16;
        cp16(sa,         &g_lph[(size_t)(m0 + arow) * NTP + k0 + ach * 8]);
        cp16(sa + 6144,  &g_lpl[(size_t)(m0 + arow) * NTP + k0 + ach * 8]);
        cp16(sa + 12288, &g_Mth[arow * NTP + k0 + ach * 8]);
        cp16(sa + 18432, &g_Mtl[arow * NTP + k0 + ach * 8]);
        cp_commit();
        cp_wait0();
        __syncthreads();

        uint32_t ah[4][4], al[4][4], bh[8], bl[8];
        #pragma unroll
        for (int mf = 0; mf < 4; ++mf) {
            ldsm4(ah[mf][0], ah[mf][1], ah[mf][2], ah[mf][3], sbase + aoff + mf * 768);
            ldsm4(al[mf][0], al[mf][1], al[mf][2], al[mf][3], sbase + 6144 + aoff + mf * 768);
        }
        ldsm4(bh[0], bh[1], bh[2], bh[3], sbase + 12288 + boff);
        ldsm4(bh[4], bh[5], bh[6], bh[7], sbase + 12288 + boff + 768);
        ldsm4(bl[0], bl[1], bl[2], bl[3], sbase + 18432 + boff);
        ldsm4(bl[4], bl[5], bl[6], bl[7], sbase + 18432 + boff + 768);
        #pragma unroll
        for (int mf = 0; mf < 4; ++mf) {
            #pragma unroll
            for (int nf = 0; nf < 4; ++nf) {
                mma_bf16(acc[mf][nf], ah[mf], bh[nf * 2], bh[nf * 2 + 1]);
                mma_bf16(acc[mf][nf], ah[mf], bl[nf * 2], bl[nf * 2 + 1]);
                mma_bf16(acc[mf][nf], al[mf], bh[nf * 2], bh[nf * 2 + 1]);
            }
        }
        __syncthreads();
    }

    #pragma unroll
    for (int mf = 0; mf < 4; ++mf) {
        int r = m0 + wm * 64 + mf * 16 + (lane >> 2);
        #pragma unroll
        for (int nf = 0; nf < 4; ++nf) {
            int c = wn * 32 + nf * 8 + (lane & 3) * 2;
            #pragma unroll
            for (int h = 0; h < 2; ++h) {
                int rr = r + h * 8;
                if (c < NCLS)     out[(size_t)rr * NCLS + c]     = acc[mf][nf][h * 2 + 0];
                if (c + 1 < NCLS) out[(size_t)rr * NCLS + c + 1] = acc[mf][nf][h * 2 + 1];
            }
        }
    }
}

// ---------------- host launch ----------------
extern "C" void kernel_launch(void* const* d_in, const int* in_sizes, int n_in,
                              void* d_out, int out_size) {
    const float *x = nullptr, *sw = nullptr, *sb = nullptr, *ll = nullptr, *tw = nullptr, *lt = nullptr;
    for (int i = 0; i < n_in; ++i) {
        switch (in_sizes[i]) {
            case BATCH * DFEAT:         x  = (const float*)d_in[i]; break;  // 8388608
            case NTREES * NINT * DFEAT: sw = (const float*)d_in[i]; break;  // 491520
            case NTREES * NINT:         sb = (const float*)d_in[i]; break;  // 480
            case NTREES * NLEAF * NCLS: ll = (const float*)d_in[i]; break;  // 51200
            case NTREES:                tw = (const float*)d_in[i]; break;  // 32
            case 1:                     lt = (const float*)d_in[i]; break;  // scalar
            default: break;
        }
    }
    float* out = (float*)d_out;

    prep_scalars_kernel<<<1, 32>>>(tw, lt);
    prep_sb_kernel<<<2, 256>>>(sb);
    prep_leaf_kernel<<<NTP, 128>>>(ll);
    split_x_kernel<<<(BATCH * DFEAT) / 1024, 256>>>(x);
    split_sw_kernel<<<(NTP * DFEAT) / 1024, 256>>>(sw);
    gemm1_kernel<<<dim3(BATCH / 128, NTP / 64), 256>>>();
    gemm2_kernel<<<BATCH / 128, 256>>>(out);
}

// round 2
// speedup vs baseline: 1.0003x; 1.0003x over previous
#include <cuda_runtime.h>
#include <cuda_bf16.h>
#include <cstdint>

#define NTREES 32
#define NINT   15
#define NLEAF  16
#define BATCH  8192
#define DFEAT  1024
#define NCLS   100
#define NTP    512   // padded tree-leaf columns (32 trees * 16 slots, slot 15 pad)
#define NCP    128   // padded class rows for GEMM2 B matrix

// ---------------- static device scratch (allocation-free contract) ----------------
__device__ __align__(16) __nv_bfloat16 g_xh[BATCH * DFEAT];
__device__ __align__(16) __nv_bfloat16 g_xl[BATCH * DFEAT];
__device__ __align__(16) __nv_bfloat16 g_swh[NTP * DFEAT];
__device__ __align__(16) __nv_bfloat16 g_swl[NTP * DFEAT];
__device__ __align__(16) float         g_sbp[NTP];
__device__ __align__(16) __nv_bfloat16 g_lph[BATCH * NTP];
__device__ __align__(16) __nv_bfloat16 g_lpl[BATCH * NTP];
__device__ __align__(16) __nv_bfloat16 g_Mth[NCP * NTP];
__device__ __align__(16) __nv_bfloat16 g_Mtl[NCP * NTP];
__device__ float g_w[NTREES];
__device__ float g_invtemp;

// ---------------- PTX helpers ----------------
__device__ __forceinline__ void cp16(uint32_t s, const void* g) {
    asm volatile("cp.async.cg.shared.global [%0], [%1], 16;\n" :: "r"(s), "l"(g));
}
__device__ __forceinline__ void cp_commit() { asm volatile("cp.async.commit_group;\n" ::); }
__device__ __forceinline__ void cp_wait0()  { asm volatile("cp.async.wait_group 0;\n" ::); }
__device__ __forceinline__ void cp_wait1()  { asm volatile("cp.async.wait_group 1;\n" ::); }

__device__ __forceinline__ void ldsm4(uint32_t& r0, uint32_t& r1, uint32_t& r2, uint32_t& r3, uint32_t a) {
    asm volatile("ldmatrix.sync.aligned.m8n8.x4.shared.b16 {%0,%1,%2,%3}, [%4];\n"
                 : "=r"(r0), "=r"(r1), "=r"(r2), "=r"(r3) : "r"(a));
}
__device__ __forceinline__ void mma_bf16(float* c, const uint32_t* a, uint32_t b0, uint32_t b1) {
    asm volatile("mma.sync.aligned.m16n8k16.row.col.f32.bf16.bf16.f32 "
                 "{%0,%1,%2,%3}, {%4,%5,%6,%7}, {%8,%9}, {%0,%1,%2,%3};\n"
                 : "+f"(c[0]), "+f"(c[1]), "+f"(c[2]), "+f"(c[3])
                 : "r"(a[0]), "r"(a[1]), "r"(a[2]), "r"(a[3]), "r"(b0), "r"(b1));
}

__device__ __forceinline__ uint32_t pack_bf16x2(__nv_bfloat16 lo, __nv_bfloat16 hi) {
    return ((uint32_t)__bfloat16_as_ushort(hi) << 16) | (uint32_t)__bfloat16_as_ushort(lo);
}

// ---------------- prep kernels ----------------
__global__ void prep_scalars_kernel(const float* __restrict__ tw, const float* __restrict__ log_temp) {
    int lane = threadIdx.x;
    float t = expf(log_temp[0]);
    t = fminf(fmaxf(t, 0.1f), 5.0f);
    if (lane == 0) g_invtemp = 1.0f / t;
    float v = tw[lane];
    float m = v;
    #pragma unroll
    for (int o = 16; o; o >>= 1) m = fmaxf(m, __shfl_xor_sync(0xffffffffu, m, o));
    float e = expf(v - m);
    float s = e;
    #pragma unroll
    for (int o = 16; o; o >>= 1) s += __shfl_xor_sync(0xffffffffu, s, o);
    g_w[lane] = e / s;
}

__global__ void prep_sb_kernel(const float* __restrict__ sb) {
    int r = blockIdx.x * blockDim.x + threadIdx.x;
    if (r < NTP) {
        int t = r >> 4, i = r & 15;
        g_sbp[r] = (i < NINT) ? sb[t * NINT + i] : 0.0f;
    }
}

// one block per (tree, leaf) column; builds M^T [class, tree*16+leaf] with tw weight folded, hi/lo split
__global__ void prep_leaf_kernel(const float* __restrict__ ll) {
    __shared__ float red[4], red2[4];
    int col = blockIdx.x;            // t*16 + l
    int t = col >> 4;
    int c = threadIdx.x;             // 0..127
    float invt = g_invtemp;
    float v = (c < NCLS) ? ll[col * NCLS + c] : -1e30f;
    float m = v;
    #pragma unroll
    for (int o = 16; o; o >>= 1) m = fmaxf(m, __shfl_xor_sync(0xffffffffu, m, o));
    if ((threadIdx.x & 31) == 0) red[threadIdx.x >> 5] = m;
    __syncthreads();
    m = fmaxf(fmaxf(red[0], red[1]), fmaxf(red[2], red[3]));
    float e = (c < NCLS) ? expf((v - m) * invt) : 0.0f;
    float s = e;
    #pragma unroll
    for (int o = 16; o; o >>= 1) s += __shfl_xor_sync(0xffffffffu, s, o);
    if ((threadIdx.x & 31) == 0) red2[threadIdx.x >> 5] = s;
    __syncthreads();
    s = red2[0] + red2[1] + red2[2] + red2[3];
    float p = (c < NCLS) ? (g_w[t] * e / s) : 0.0f;
    __nv_bfloat16 h = __float2bfloat16_rn(p);
    g_Mth[c * NTP + col] = h;
    g_Mtl[c * NTP + col] = __float2bfloat16_rn(p - __bfloat162float(h));
}

__global__ void split_x_kernel(const float* __restrict__ x) {
    int i = (blockIdx.x * blockDim.x + threadIdx.x) * 4;
    float4 v = *reinterpret_cast<const float4*>(x + i);
    __nv_bfloat16 h0 = __float2bfloat16_rn(v.x), h1 = __float2bfloat16_rn(v.y);
    __nv_bfloat16 h2 = __float2bfloat16_rn(v.z), h3 = __float2bfloat16_rn(v.w);
    __nv_bfloat16 l0 = __float2bfloat16_rn(v.x - __bfloat162float(h0));
    __nv_bfloat16 l1 = __float2bfloat16_rn(v.y - __bfloat162float(h1));
    __nv_bfloat16 l2 = __float2bfloat16_rn(v.z - __bfloat162float(h2));
    __nv_bfloat16 l3 = __float2bfloat16_rn(v.w - __bfloat162float(h3));
    uint2 H, L;
    H.x = pack_bf16x2(h0, h1); H.y = pack_bf16x2(h2, h3);
    L.x = pack_bf16x2(l0, l1); L.y = pack_bf16x2(l2, l3);
    *reinterpret_cast<uint2*>(&g_xh[i]) = H;
    *reinterpret_cast<uint2*>(&g_xl[i]) = L;
}

__global__ void split_sw_kernel(const float* __restrict__ sw) {
    int idx = (blockIdx.x * blockDim.x + threadIdx.x) * 4;   // over NTP*DFEAT
    int row = idx >> 10;
    int k = idx & 1023;
    int t = row >> 4, i = row & 15;
    float4 v = make_float4(0.f, 0.f, 0.f, 0.f);
    if (i < NINT) v = *reinterpret_cast<const float4*>(&sw[(size_t)(t * NINT + i) * DFEAT + k]);
    __nv_bfloat16 h0 = __float2bfloat16_rn(v.x), h1 = __float2bfloat16_rn(v.y);
    __nv_bfloat16 h2 = __float2bfloat16_rn(v.z), h3 = __float2bfloat16_rn(v.w);
    __nv_bfloat16 l0 = __float2bfloat16_rn(v.x - __bfloat162float(h0));
    __nv_bfloat16 l1 = __float2bfloat16_rn(v.y - __bfloat162float(h1));
    __nv_bfloat16 l2 = __float2bfloat16_rn(v.z - __bfloat162float(h2));
    __nv_bfloat16 l3 = __float2bfloat16_rn(v.w - __bfloat162float(h3));
    uint2 H, L;
    H.x = pack_bf16x2(h0, h1); H.y = pack_bf16x2(h2, h3);
    L.x = pack_bf16x2(l0, l1); L.y = pack_bf16x2(l2, l3);
    *reinterpret_cast<uint2*>(&g_swh[idx]) = H;
    *reinterpret_cast<uint2*>(&g_swl[idx]) = L;
}

// ---------------- GEMM1: sp = sigmoid((x@sw^T + sb)/temp), fused leaf-prob epilogue ----------------
// Block tile 128(M) x 64(N=4 trees) x 16(K), 2-stage cp.async pipeline, 3-pass bf16 split.
#define G1_STAGE 18432   // Ah 6144 + Al 6144 + Bh 3072 + Bl 3072 (rows padded to 24 bf16 = 48 B)

__global__ void __launch_bounds__(256, 1) gemm1_kernel() {
    __shared__ __align__(16) unsigned char smem[2 * G1_STAGE];
    const uint32_t sbase = (uint32_t)__cvta_generic_to_shared(smem);
    const int tid = threadIdx.x;
    const int m0 = blockIdx.x * 128;
    const int n0 = blockIdx.y * 64;
    const int wid = tid >> 5, lane = tid & 31;
    const int wm = wid >> 2, wn = wid & 3;

    float acc[4][2][4];
    #pragma unroll
    for (int i = 0; i < 4; i++)
        #pragma unroll
        for (int j = 0; j < 2; j++)
            #pragma unroll
            for (int k = 0; k < 4; k++) acc[i][j][k] = 0.0f;

    const int arow = tid >> 1, ach = tid & 1;        // 128 rows x 2 16B chunks
    const int bt = tid & 127;
    const int brow = bt >> 1, bch = bt & 1;          // 64 rows x 2 chunks

    auto issue = [&](int s, int k0) {
        uint32_t st = sbase + s * G1_STAGE;
        uint32_t sa = st + arow * 48 + ach * 16;
        cp16(sa,        &g_xh[(m0 + arow) * DFEAT + k0 + ach * 8]);
        cp16(sa + 6144, &g_xl[(m0 + arow) * DFEAT + k0 + ach * 8]);
        uint32_t sbm = st + 12288 + (tid >= 128 ? 3072 : 0) + brow * 48 + bch * 16;
        const __nv_bfloat16* bsrc = (tid >= 128)
            ? &g_swl[(n0 + brow) * DFEAT + k0 + bch * 8]
            : &g_swh[(n0 + brow) * DFEAT + k0 + bch * 8];
        cp16(sbm, bsrc);
    };

    issue(0, 0);
    cp_commit();

    const uint32_t aoff = (uint32_t)((wm * 64 + (lane & 15)) * 48 + (lane >> 4) * 16);
    const uint32_t boff = (uint32_t)((wn * 16 + (lane & 7) + ((lane >> 4) << 3)) * 48 + (((lane >> 3) & 1) << 4));

    #pragma unroll 1
    for (int kt = 0; kt < DFEAT / 16; ++kt) {
        if (kt + 1 < DFEAT / 16) { issue((kt + 1) & 1, (kt + 1) * 16); cp_commit(); cp_wait1(); }
        else cp_wait0();
        __syncthreads();
        uint32_t st = sbase + (kt & 1) * G1_STAGE;
        uint32_t ah[4][4], al[4][4], bh[4], bl[4];
        #pragma unroll
        for (int mf = 0; mf < 4; ++mf) {
            ldsm4(ah[mf][0], ah[mf][1], ah[mf][2], ah[mf][3], st + aoff + mf * 768);
            ldsm4(al[mf][0], al[mf][1], al[mf][2], al[mf][3], st + 6144 + aoff + mf * 768);
        }
        ldsm4(bh[0], bh[1], bh[2], bh[3], st + 12288 + boff);
        ldsm4(bl[0], bl[1], bl[2], bl[3], st + 15360 + boff);
        #pragma unroll
        for (int mf = 0; mf < 4; ++mf) {
            #pragma unroll
            for (int nf = 0; nf < 2; ++nf) {
                mma_bf16(acc[mf][nf], ah[mf], bh[nf * 2], bh[nf * 2 + 1]);
                mma_bf16(acc[mf][nf], ah[mf], bl[nf * 2], bl[nf * 2 + 1]);
                mma_bf16(acc[mf][nf], al[mf], bh[nf * 2], bh[nf * 2 + 1]);
            }
        }
        __syncthreads();
    }

    // Epilogue 1: sigmoid -> sp scratch in smem (stride 68 floats)
    float* sp = reinterpret_cast<float*>(smem);
    const float invt = g_invtemp;
    #pragma unroll
    for (int mf = 0; mf < 4; ++mf) {
        int r = wm * 64 + mf * 16 + (lane >> 2);
        #pragma unroll
        for (int nf = 0; nf < 2; ++nf) {
            int c = wn * 16 + nf * 8 + (lane & 3) * 2;
            float b0 = g_sbp[n0 + c], b1 = g_sbp[n0 + c + 1];
            #pragma unroll
            for (int h = 0; h < 2; ++h) {
                float z0 = (acc[mf][nf][h * 2 + 0] + b0) * invt;
                float z1 = (acc[mf][nf][h * 2 + 1] + b1) * invt;
                sp[(r + h * 8) * 68 + c]     = 1.0f / (1.0f + __expf(-z0));
                sp[(r + h * 8) * 68 + c + 1] = 1.0f / (1.0f + __expf(-z1));
            }
        }
    }
    __syncthreads();

    // Epilogue 2: each (row, tree) -> 16 leaf path-products, store bf16 hi/lo
    #pragma unroll
    for (int pass = 0; pass < 2; ++pass) {
        int task = pass * 256 + tid;      // 512 tasks = 128 rows * 4 trees
        int row = task >> 2, tr = task & 3;
        float s[15];
        #pragma unroll
        for (int i = 0; i < 15; ++i) s[i] = sp[row * 68 + tr * 16 + i];
        alignas(16) __nv_bfloat16 ph[16];
        alignas(16) __nv_bfloat16 pl[16];
        #pragma unroll
        for (int l = 0; l < 16; ++l) {
            float p = 1.0f;
            int ni = l + 15;
            #pragma unroll
            for (int d = 0; d < 4; ++d) {
                int pi = (ni - 1) >> 1;
                float f = s[pi];
                p *= (ni & 1) ? (1.0f - f) : f;   // even child -> sp, odd -> 1-sp
                ni = pi;
            }
            __nv_bfloat16 h = __float2bfloat16_rn(p);
            ph[l] = h;
            pl[l] = __float2bfloat16_rn(p - __bfloat162float(h));
        }
        size_t off = (size_t)(m0 + row) * NTP + n0 + tr * 16;
        const uint4* uh = reinterpret_cast<const uint4*>(ph);
        const uint4* ul = reinterpret_cast<const uint4*>(pl);
        reinterpret_cast<uint4*>(&g_lph[off])[0] = uh[0];
        reinterpret_cast<uint4*>(&g_lph[off])[1] = uh[1];
        reinterpret_cast<uint4*>(&g_lpl[off])[0] = ul[0];
        reinterpret_cast<uint4*>(&g_lpl[off])[1] = ul[1];
    }
}

// ---------------- GEMM2: out = lp[8192,512] @ M^T, 128x128x16 tiles, split bf16 ----------------
__global__ void __launch_bounds__(256, 1) gemm2_kernel(float* __restrict__ out) {
    __shared__ __align__(16) unsigned char smem[24576]; // Ah 6144 | Al 6144 | Bh 6144 | Bl 6144
    const uint32_t sbase = (uint32_t)__cvta_generic_to_shared(smem);
    const int tid = threadIdx.x;
    const int m0 = blockIdx.x * 128;
    const int wid = tid >> 5, lane = tid & 31;
    const int wm = wid >> 2, wn = wid & 3;

    float acc[4][4][4];
    #pragma unroll
    for (int i = 0; i < 4; i++)
        #pragma unroll
        for (int j = 0; j < 4; j++)
            #pragma unroll
            for (int k = 0; k < 4; k++) acc[i][j][k] = 0.0f;

    const int arow = tid >> 1, ach = tid & 1;    // 128 rows x 2 chunks for both A and B tiles
    const uint32_t aoff = (uint32_t)((wm * 64 + (lane & 15)) * 48 + (lane >> 4) * 16);
    const uint32_t boff = (uint32_t)((wn * 32 + (lane & 7) + ((lane >> 4) << 3)) * 48 + (((lane >> 3) & 1) << 4));

    #pragma unroll 1
    for (int kt = 0; kt < NTP / 16; ++kt) {
        int k0 = kt * 16;
        uint32_t sa = sbase + arow * 48 + ach * 16;
        cp16(sa,         &g_lph[(size_t)(m0 + arow) * NTP + k0 + ach * 8]);
        cp16(sa + 6144,  &g_lpl[(size_t)(m0 + arow) * NTP + k0 + ach * 8]);
        cp16(sa + 12288, &g_Mth[arow * NTP + k0 + ach * 8]);
        cp16(sa + 18432, &g_Mtl[arow * NTP + k0 + ach * 8]);
        cp_commit();
        cp_wait0();
        __syncthreads();

        uint32_t ah[4][4], al[4][4], bh[8], bl[8];
        #pragma unroll
        for (int mf = 0; mf < 4; ++mf) {
            ldsm4(ah[mf][0], ah[mf][1], ah[mf][2], ah[mf][3], sbase + aoff + mf * 768);
            ldsm4(al[mf][0], al[mf][1], al[mf][2], al[mf][3], sbase + 6144 + aoff + mf * 768);
        }
        ldsm4(bh[0], bh[1], bh[2], bh[3], sbase + 12288 + boff);
        ldsm4(bh[4], bh[5], bh[6], bh[7], sbase + 12288 + boff + 768);
        ldsm4(bl[0], bl[1], bl[2], bl[3], sbase + 18432 + boff);
        ldsm4(bl[4], bl[5], bl[6], bl[7], sbase + 18432 + boff + 768);
        #pragma unroll
        for (int mf = 0; mf < 4; ++mf) {
            #pragma unroll
            for (int nf = 0; nf < 4; ++nf) {
                mma_bf16(acc[mf][nf], ah[mf], bh[nf * 2], bh[nf * 2 + 1]);
                mma_bf16(acc[mf][nf], ah[mf], bl[nf * 2], bl[nf * 2 + 1]);
                mma_bf16(acc[mf][nf], al[mf], bh[nf * 2], bh[nf * 2 + 1]);
            }
        }
        __syncthreads();
    }

    #pragma unroll
    for (int mf = 0; mf < 4; ++mf) {
        int r = m0 + wm * 64 + mf * 16 + (lane >> 2);
        #pragma unroll
        for (int nf = 0; nf < 4; ++nf) {
            int c = wn * 32 + nf * 8 + (lane & 3) * 2;
            #pragma unroll
            for (int h = 0; h < 2; ++h) {
                int rr = r + h * 8;
                if (c < NCLS)     out[(size_t)rr * NCLS + c]     = acc[mf][nf][h * 2 + 0];
                if (c + 1 < NCLS) out[(size_t)rr * NCLS + c + 1] = acc[mf][nf][h * 2 + 1];
            }
        }
    }
}

// ---------------- host launch ----------------
extern "C" void kernel_launch(void* const* d_in, const int* in_sizes, int n_in,
                              void* d_out, int out_size) {
    const float *x = nullptr, *sw = nullptr, *sb = nullptr, *ll = nullptr, *tw = nullptr, *lt = nullptr;
    for (int i = 0; i < n_in; ++i) {
        switch (in_sizes[i]) {
            case BATCH * DFEAT:         x  = (const float*)d_in[i]; break;  // 8388608
            case NTREES * NINT * DFEAT: sw = (const float*)d_in[i]; break;  // 491520
            case NTREES * NINT:         sb = (const float*)d_in[i]; break;  // 480
            case NTREES * NLEAF * NCLS: ll = (const float*)d_in[i]; break;  // 51200
            case NTREES:                tw = (const float*)d_in[i]; break;  // 32
            case 1:                     lt = (const float*)d_in[i]; break;  // scalar
            default: break;
        }
    }
    float* out = (float*)d_out;

    prep_scalars_kernel<<<1, 32>>>(tw, lt);
    prep_sb_kernel<<<2, 256>>>(sb);
    prep_leaf_kernel<<<NTP, 128>>>(ll);
    split_x_kernel<<<(BATCH * DFEAT) / 1024, 256>>>(x);
    split_sw_kernel<<<(NTP * DFEAT) / 1024, 256>>>(sw);
    gemm1_kernel<<<dim3(BATCH / 128, NTP / 64), 256>>>();
    gemm2_kernel<<<BATCH / 128, 256>>>(out);
}

// round 5
// speedup vs baseline: 1.5735x; 1.5731x over previous
#include <cuda_runtime.h>
#include <cuda_bf16.h>
#include <cstdint>

#define NTREES 32
#define NINT   15
#define NLEAF  16
#define BATCH  8192
#define DFEAT  1024
#define NCLS   100
#define NTP    512   // 32 trees * 16 padded internal / leaf slots
#define NCP    128   // padded class rows for GEMM2 B

// ---------------- static device scratch ----------------
__device__ __align__(16) __nv_bfloat16 g_xh[BATCH * DFEAT];
__device__ __align__(16) __nv_bfloat16 g_xl[BATCH * DFEAT];
__device__ __align__(16) __nv_bfloat16 g_swh[NTP * DFEAT];
__device__ __align__(16) __nv_bfloat16 g_swl[NTP * DFEAT];
__device__ __align__(16) float         g_sbp[NTP];
__device__ __align__(16) __nv_bfloat16 g_lph[BATCH * NTP];
__device__ __align__(16) __nv_bfloat16 g_lpl[BATCH * NTP];
__device__ __align__(16) __nv_bfloat16 g_Mth[NCP * NTP];
__device__ __align__(16) __nv_bfloat16 g_Mtl[NCP * NTP];
__device__ float g_w[NTREES];
__device__ float g_invtemp;

// ---------------- PTX helpers ----------------
__device__ __forceinline__ uint32_t smem_u32(const void* p) {
    return (uint32_t)__cvta_generic_to_shared(p);
}
__device__ __forceinline__ void cp16(uint32_t s, const void* g) {
    asm volatile("cp.async.cg.shared.global [%0], [%1], 16;\n" :: "r"(s), "l"(g));
}
__device__ __forceinline__ void cp_commit() { asm volatile("cp.async.commit_group;\n" ::); }
__device__ __forceinline__ void cp_wait0()  { asm volatile("cp.async.wait_group 0;\n" ::); }
__device__ __forceinline__ void cp_wait1()  { asm volatile("cp.async.wait_group 1;\n" ::); }

__device__ __forceinline__ void ldsm4(uint32_t* r, uint32_t a) {
    asm volatile("ldmatrix.sync.aligned.m8n8.x4.shared.b16 {%0,%1,%2,%3}, [%4];\n"
                 : "=r"(r[0]), "=r"(r[1]), "=r"(r[2]), "=r"(r[3]) : "r"(a));
}
__device__ __forceinline__ void mma_bf16(float* c, const uint32_t* a, uint32_t b0, uint32_t b1) {
    asm volatile("mma.sync.aligned.m16n8k16.row.col.f32.bf16.bf16.f32 "
                 "{%0,%1,%2,%3}, {%4,%5,%6,%7}, {%8,%9}, {%0,%1,%2,%3};\n"
                 : "+f"(c[0]), "+f"(c[1]), "+f"(c[2]), "+f"(c[3])
                 : "r"(a[0]), "r"(a[1]), "r"(a[2]), "r"(a[3]), "r"(b0), "r"(b1));
}

__device__ __forceinline__ uint32_t pack_bf16x2(__nv_bfloat16 lo, __nv_bfloat16 hi) {
    return ((uint32_t)__bfloat16_as_ushort(hi) << 16) | (uint32_t)__bfloat16_as_ushort(lo);
}

// ---------------- prep kernels ----------------
__global__ void prep_scalars_kernel(const float* __restrict__ tw, const float* __restrict__ log_temp) {
    int lane = threadIdx.x;
    float t = expf(log_temp[0]);
    t = fminf(fmaxf(t, 0.1f), 5.0f);
    if (lane == 0) g_invtemp = 1.0f / t;
    float v = tw[lane];
    float m = v;
    #pragma unroll
    for (int o = 16; o; o >>= 1) m = fmaxf(m, __shfl_xor_sync(0xffffffffu, m, o));
    float e = expf(v - m);
    float s = e;
    #pragma unroll
    for (int o = 16; o; o >>= 1) s += __shfl_xor_sync(0xffffffffu, s, o);
    g_w[lane] = e / s;
}

__global__ void prep_sb_kernel(const float* __restrict__ sb) {
    int r = blockIdx.x * blockDim.x + threadIdx.x;
    if (r < NTP) {
        int t = r >> 4, i = r & 15;
        g_sbp[r] = (i < NINT) ? sb[t * NINT + i] : 0.0f;
    }
}

__global__ void prep_leaf_kernel(const float* __restrict__ ll) {
    __shared__ float red[4], red2[4];
    int col = blockIdx.x;            // t*16 + l
    int t = col >> 4;
    int c = threadIdx.x;             // 0..127
    float invt = g_invtemp;
    float v = (c < NCLS) ? ll[col * NCLS + c] : -1e30f;
    float m = v;
    #pragma unroll
    for (int o = 16; o; o >>= 1) m = fmaxf(m, __shfl_xor_sync(0xffffffffu, m, o));
    if ((threadIdx.x & 31) == 0) red[threadIdx.x >> 5] = m;
    __syncthreads();
    m = fmaxf(fmaxf(red[0], red[1]), fmaxf(red[2], red[3]));
    float e = (c < NCLS) ? expf((v - m) * invt) : 0.0f;
    float s = e;
    #pragma unroll
    for (int o = 16; o; o >>= 1) s += __shfl_xor_sync(0xffffffffu, s, o);
    if ((threadIdx.x & 31) == 0) red2[threadIdx.x >> 5] = s;
    __syncthreads();
    s = red2[0] + red2[1] + red2[2] + red2[3];
    float p = (c < NCLS) ? (g_w[t] * e / s) : 0.0f;
    __nv_bfloat16 h = __float2bfloat16_rn(p);
    g_Mth[c * NTP + col] = h;
    g_Mtl[c * NTP + col] = __float2bfloat16_rn(p - __bfloat162float(h));
}

__global__ void split_x_kernel(const float* __restrict__ x) {
    int i = (blockIdx.x * blockDim.x + threadIdx.x) * 4;
    float4 v = *reinterpret_cast<const float4*>(x + i);
    __nv_bfloat16 h0 = __float2bfloat16_rn(v.x), h1 = __float2bfloat16_rn(v.y);
    __nv_bfloat16 h2 = __float2bfloat16_rn(v.z), h3 = __float2bfloat16_rn(v.w);
    __nv_bfloat16 l0 = __float2bfloat16_rn(v.x - __bfloat162float(h0));
    __nv_bfloat16 l1 = __float2bfloat16_rn(v.y - __bfloat162float(h1));
    __nv_bfloat16 l2 = __float2bfloat16_rn(v.z - __bfloat162float(h2));
    __nv_bfloat16 l3 = __float2bfloat16_rn(v.w - __bfloat162float(h3));
    uint2 H, L;
    H.x = pack_bf16x2(h0, h1); H.y = pack_bf16x2(h2, h3);
    L.x = pack_bf16x2(l0, l1); L.y = pack_bf16x2(l2, l3);
    *reinterpret_cast<uint2*>(&g_xh[i]) = H;
    *reinterpret_cast<uint2*>(&g_xl[i]) = L;
}

__global__ void split_sw_kernel(const float* __restrict__ sw) {
    int idx = (blockIdx.x * blockDim.x + threadIdx.x) * 4;   // over NTP*DFEAT
    int row = idx >> 10;
    int k = idx & 1023;
    int t = row >> 4, i = row & 15;
    float4 v = make_float4(0.f, 0.f, 0.f, 0.f);
    if (i < NINT) v = *reinterpret_cast<const float4*>(&sw[(size_t)(t * NINT + i) * DFEAT + k]);
    __nv_bfloat16 h0 = __float2bfloat16_rn(v.x), h1 = __float2bfloat16_rn(v.y);
    __nv_bfloat16 h2 = __float2bfloat16_rn(v.z), h3 = __float2bfloat16_rn(v.w);
    __nv_bfloat16 l0 = __float2bfloat16_rn(v.x - __bfloat162float(h0));
    __nv_bfloat16 l1 = __float2bfloat16_rn(v.y - __bfloat162float(h1));
    __nv_bfloat16 l2 = __float2bfloat16_rn(v.z - __bfloat162float(h2));
    __nv_bfloat16 l3 = __float2bfloat16_rn(v.w - __bfloat162float(h3));
    uint2 H, L;
    H.x = pack_bf16x2(h0, h1); H.y = pack_bf16x2(h2, h3);
    L.x = pack_bf16x2(l0, l1); L.y = pack_bf16x2(l2, l3);
    *reinterpret_cast<uint2*>(&g_swh[idx]) = H;
    *reinterpret_cast<uint2*>(&g_swl[idx]) = L;
}

// ================= GEMM1 (mma.sync): 128x128 tile, K-chunk 32, 2-stage, 2 CTA/SM =================
// Stage layout (row stride 80B = 64B data + 16B pad):
//   Ah @0 (128*80=10240) | Al @10240 | Bh @20480 | Bl @30720 ; stage = 40960
#define G1_STAGE 40960
#define G1_HDR   1024
#define G1_SMEM  (G1_HDR + 2 * G1_STAGE)   // 82944

__global__ void __launch_bounds__(256, 2) gemm1_ms() {
    extern __shared__ __align__(16) unsigned char sm1[];
    const uint32_t sbase = smem_u32(sm1);
    const int tid = threadIdx.x;
    const int wid = tid >> 5, lane = tid & 31;
    const int wm = wid >> 2, wn = wid & 3;           // 2 x 4 warp grid, warp tile 64x32
    const int m0 = blockIdx.x * 128;
    const int n0 = blockIdx.y * 128;

    float* s_sb = reinterpret_cast<float*>(sm1 + 64);
    if (tid < 128) s_sb[tid] = g_sbp[n0 + tid];

    float acc[4][4][4];
    #pragma unroll
    for (int i = 0; i < 4; i++)
        #pragma unroll
        for (int j = 0; j < 4; j++)
            #pragma unroll
            for (int k = 0; k < 4; k++) acc[i][j][k] = 0.0f;

    auto issue = [&](int s, int k0) {
        const uint32_t S = sbase + G1_HDR + s * G1_STAGE;
        #pragma unroll
        for (int it = 0; it < 2; ++it) {
            int c = tid + it * 256;                  // 512 chunks per matrix
            int r = c >> 2, kc = c & 3;
            uint32_t so = (uint32_t)(r * 80 + kc * 16);
            size_t ga = (size_t)(m0 + r) * DFEAT + k0 + kc * 8;
            size_t gb = (size_t)(n0 + r) * DFEAT + k0 + kc * 8;
            cp16(S + so,         &g_xh[ga]);
            cp16(S + 10240 + so, &g_xl[ga]);
            cp16(S + 20480 + so, &g_swh[gb]);
            cp16(S + 30720 + so, &g_swl[gb]);
        }
    };

    issue(0, 0);
    cp_commit();

    const uint32_t a_off = (uint32_t)((wm * 64 + (lane & 15)) * 80 + (lane >> 4) * 16);
    const uint32_t b_off = (uint32_t)((wn * 32 + (lane & 7) + ((lane >> 4) << 3)) * 80
                                      + (((lane >> 3) & 1) << 4));

    #pragma unroll 1
    for (int c = 0; c < DFEAT / 32; ++c) {
        if (c + 1 < DFEAT / 32) { issue((c + 1) & 1, (c + 1) * 32); cp_commit(); cp_wait1(); }
        else cp_wait0();
        __syncthreads();
        const uint32_t S = sbase + G1_HDR + (c & 1) * G1_STAGE;
        #pragma unroll
        for (int kf = 0; kf < 2; ++kf) {
            uint32_t ah[4][4], al[4][4];
            #pragma unroll
            for (int mf = 0; mf < 4; ++mf) {
                ldsm4(ah[mf], S + a_off + mf * 1280 + kf * 32);
                ldsm4(al[mf], S + 10240 + a_off + mf * 1280 + kf * 32);
            }
            {
                uint32_t bh[2][4];
                #pragma unroll
                for (int g = 0; g < 2; ++g)
                    ldsm4(bh[g], S + 20480 + b_off + g * 1280 + kf * 32);
                #pragma unroll
                for (int mf = 0; mf < 4; ++mf)
                    #pragma unroll
                    for (int g = 0; g < 2; ++g) {
                        mma_bf16(acc[mf][2 * g],     ah[mf], bh[g][0], bh[g][1]);
                        mma_bf16(acc[mf][2 * g + 1], ah[mf], bh[g][2], bh[g][3]);
                        mma_bf16(acc[mf][2 * g],     al[mf], bh[g][0], bh[g][1]);
                        mma_bf16(acc[mf][2 * g + 1], al[mf], bh[g][2], bh[g][3]);
                    }
            }
            {
                uint32_t bl[2][4];
                #pragma unroll
                for (int g = 0; g < 2; ++g)
                    ldsm4(bl[g], S + 30720 + b_off + g * 1280 + kf * 32);
                #pragma unroll
                for (int mf = 0; mf < 4; ++mf)
                    #pragma unroll
                    for (int g = 0; g < 2; ++g) {
                        mma_bf16(acc[mf][2 * g],     ah[mf], bl[g][0], bl[g][1]);
                        mma_bf16(acc[mf][2 * g + 1], ah[mf], bl[g][2], bl[g][3]);
                    }
            }
        }
        __syncthreads();
    }

    // Epilogue 1: bias + sigmoid -> sp scratch (reuse stage smem), stride 132 floats
    float* sp = reinterpret_cast<float*>(sm1 + G1_HDR);
    const float invt = g_invtemp;
    #pragma unroll
    for (int mf = 0; mf < 4; ++mf) {
        int r = wm * 64 + mf * 16 + (lane >> 2);
        #pragma unroll
        for (int nf = 0; nf < 4; ++nf) {
            int cc = wn * 32 + nf * 8 + (lane & 3) * 2;
            float b0 = s_sb[cc], b1 = s_sb[cc + 1];
            #pragma unroll
            for (int h = 0; h < 2; ++h) {
                float z0 = (acc[mf][nf][h * 2 + 0] + b0) * invt;
                float z1 = (acc[mf][nf][h * 2 + 1] + b1) * invt;
                sp[(r + h * 8) * 132 + cc]     = 1.0f / (1.0f + __expf(-z0));
                sp[(r + h * 8) * 132 + cc + 1] = 1.0f / (1.0f + __expf(-z1));
            }
        }
    }
    __syncthreads();

    // Epilogue 2: 128 rows x 8 trees -> leaf products, bf16 hi/lo out
    #pragma unroll
    for (int pass = 0; pass < 4; ++pass) {
        int task = pass * 256 + tid;      // 1024 tasks
        int row = task >> 3, tr = task & 7;
        float s[15];
        #pragma unroll
        for (int i = 0; i < 15; ++i) s[i] = sp[row * 132 + tr * 16 + i];
        alignas(16) __nv_bfloat16 ph[16];
        alignas(16) __nv_bfloat16 pl[16];
        #pragma unroll
        for (int l = 0; l < 16; ++l) {
            float p = 1.0f;
            int ni = l + 15;
            #pragma unroll
            for (int d = 0; d < 4; ++d) {
                int pi = (ni - 1) >> 1;
                float f = s[pi];
                p *= (ni & 1) ? (1.0f - f) : f;
                ni = pi;
            }
            __nv_bfloat16 h = __float2bfloat16_rn(p);
            ph[l] = h;
            pl[l] = __float2bfloat16_rn(p - __bfloat162float(h));
        }
        size_t off = (size_t)(m0 + row) * NTP + n0 + tr * 16;
        const uint4* uh = reinterpret_cast<const uint4*>(ph);
        const uint4* ul = reinterpret_cast<const uint4*>(pl);
        reinterpret_cast<uint4*>(&g_lph[off])[0] = uh[0];
        reinterpret_cast<uint4*>(&g_lph[off])[1] = uh[1];
        reinterpret_cast<uint4*>(&g_lpl[off])[0] = ul[0];
        reinterpret_cast<uint4*>(&g_lpl[off])[1] = ul[1];
    }
}

// ================= GEMM2 (mma.sync): out = lp[8192,512] @ M^T, BM=64 BN=128 BK=32 =================
// Stage: Ah @0 (64*80=5120) | Al @5120 | Bh @10240 (128*80) | Bl @20480 ; stage = 30720
#define G2_STAGE 30720
#define G2_HDR   1024
#define G2_SMEM  (G2_HDR + 2 * G2_STAGE)   // 62464

__global__ void __launch_bounds__(256, 2) gemm2_ms(float* __restrict__ out) {
    extern __shared__ __align__(16) unsigned char sm2[];
    const uint32_t sbase = smem_u32(sm2);
    const int tid = threadIdx.x;
    const int wid = tid >> 5, lane = tid & 31;
    const int wm = wid >> 2, wn = wid & 3;           // warp tile 32x32
    const int m0 = blockIdx.x * 64;

    float acc[2][4][4];
    #pragma unroll
    for (int i = 0; i < 2; i++)
        #pragma unroll
        for (int j = 0; j < 4; j++)
            #pragma unroll
            for (int k = 0; k < 4; k++) acc[i][j][k] = 0.0f;

    auto issue = [&](int s, int k0) {
        const uint32_t S = sbase + G2_HDR + s * G2_STAGE;
        {   // A: 256 chunks hi + 256 lo
            int c = tid;
            int r = c >> 2, kc = c & 3;
            uint32_t so = (uint32_t)(r * 80 + kc * 16);
            size_t ga = (size_t)(m0 + r) * NTP + k0 + kc * 8;
            cp16(S + so,        &g_lph[ga]);
            cp16(S + 5120 + so, &g_lpl[ga]);
        }
        #pragma unroll
        for (int it = 0; it < 2; ++it) {   // B: 512 chunks hi + 512 lo
            int c = tid + it * 256;
            int r = c >> 2, kc = c & 3;
            uint32_t so = (uint32_t)(r * 80 + kc * 16);
            size_t gb = (size_t)r * NTP + k0 + kc * 8;
            cp16(S + 10240 + so, &g_Mth[gb]);
            cp16(S + 20480 + so, &g_Mtl[gb]);
        }
    };

    issue(0, 0);
    cp_commit();

    const uint32_t a_off = (uint32_t)((wm * 32 + (lane & 15)) * 80 + (lane >> 4) * 16);
    const uint32_t b_off = (uint32_t)((wn * 32 + (lane & 7) + ((lane >> 4) << 3)) * 80
                                      + (((lane >> 3) & 1) << 4));

    #pragma unroll 1
    for (int c = 0; c < NTP / 32; ++c) {
        if (c + 1 < NTP / 32) { issue((c + 1) & 1, (c + 1) * 32); cp_commit(); cp_wait1(); }
        else cp_wait0();
        __syncthreads();
        const uint32_t S = sbase + G2_HDR + (c & 1) * G2_STAGE;
        #pragma unroll
        for (int kf = 0; kf < 2; ++kf) {
            uint32_t ah[2][4], al[2][4];
            #pragma unroll
            for (int mf = 0; mf < 2; ++mf) {
                ldsm4(ah[mf], S + a_off + mf * 1280 + kf * 32);
                ldsm4(al[mf], S + 5120 + a_off + mf * 1280 + kf * 32);
            }
            {
                uint32_t bh[2][4];
                #pragma unroll
                for (int g = 0; g < 2; ++g)
                    ldsm4(bh[g], S + 10240 + b_off + g * 1280 + kf * 32);
                #pragma unroll
                for (int mf = 0; mf < 2; ++mf)
                    #pragma unroll
                    for (int g = 0; g < 2; ++g) {
                        mma_bf16(acc[mf][2 * g],     ah[mf], bh[g][0], bh[g][1]);
                        mma_bf16(acc[mf][2 * g + 1], ah[mf], bh[g][2], bh[g][3]);
                        mma_bf16(acc[mf][2 * g],     al[mf], bh[g][0], bh[g][1]);
                        mma_bf16(acc[mf][2 * g + 1], al[mf], bh[g][2], bh[g][3]);
                    }
            }
            {
                uint32_t bl[2][4];
                #pragma unroll
                for (int g = 0; g < 2; ++g)
                    ldsm4(bl[g], S + 20480 + b_off + g * 1280 + kf * 32);
                #pragma unroll
                for (int mf = 0; mf < 2; ++mf)
                    #pragma unroll
                    for (int g = 0; g < 2; ++g) {
                        mma_bf16(acc[mf][2 * g],     ah[mf], bl[g][0], bl[g][1]);
                        mma_bf16(acc[mf][2 * g + 1], ah[mf], bl[g][2], bl[g][3]);
                    }
            }
        }
        __syncthreads();
    }

    #pragma unroll
    for (int mf = 0; mf < 2; ++mf) {
        int r = m0 + wm * 32 + mf * 16 + (lane >> 2);
        #pragma unroll
        for (int nf = 0; nf < 4; ++nf) {
            int cc = wn * 32 + nf * 8 + (lane & 3) * 2;
            #pragma unroll
            for (int h = 0; h < 2; ++h) {
                int rr = r + h * 8;
                if (cc < NCLS)     out[(size_t)rr * NCLS + cc]     = acc[mf][nf][h * 2 + 0];
                if (cc + 1 < NCLS) out[(size_t)rr * NCLS + cc + 1] = acc[mf][nf][h * 2 + 1];
            }
        }
    }
}

// ---------------- host launch ----------------
extern "C" void kernel_launch(void* const* d_in, const int* in_sizes, int n_in,
                              void* d_out, int out_size) {
    const float *x = nullptr, *sw = nullptr, *sb = nullptr, *ll = nullptr, *tw = nullptr, *lt = nullptr;
    for (int i = 0; i < n_in; ++i) {
        switch (in_sizes[i]) {
            case BATCH * DFEAT:         x  = (const float*)d_in[i]; break;
            case NTREES * NINT * DFEAT: sw = (const float*)d_in[i]; break;
            case NTREES * NINT:         sb = (const float*)d_in[i]; break;
            case NTREES * NLEAF * NCLS: ll = (const float*)d_in[i]; break;
            case NTREES:                tw = (const float*)d_in[i]; break;
            case 1:                     lt = (const float*)d_in[i]; break;
            default: break;
        }
    }
    float* out = (float*)d_out;

    cudaFuncSetAttribute(gemm1_ms, cudaFuncAttributeMaxDynamicSharedMemorySize, G1_SMEM);
    cudaFuncSetAttribute(gemm2_ms, cudaFuncAttributeMaxDynamicSharedMemorySize, G2_SMEM);

    prep_scalars_kernel<<<1, 32>>>(tw, lt);
    prep_sb_kernel<<<2, 256>>>(sb);
    prep_leaf_kernel<<<NTP, 128>>>(ll);
    split_x_kernel<<<(BATCH * DFEAT) / 1024, 256>>>(x);
    split_sw_kernel<<<(NTP * DFEAT) / 1024, 256>>>(sw);
    gemm1_ms<<<dim3(BATCH / 128, NTP / 128), 256, G1_SMEM>>>();
    gemm2_ms<<<BATCH / 64, 256, G2_SMEM>>>(out);
}